// round 15
// baseline (speedup 1.0000x reference)
#include <cuda_runtime.h>
#include <cuda_bf16.h>
#include <cstdint>

#define NN 20000
#define EE 500000
#define KK 48

// ---------------- device scratch (no allocations allowed) ----------------
struct __align__(16) ERec { float b[8]; unsigned kx[2]; int src; int pad; };  // 48B

__device__ __align__(16) float    g_basis [EE * 8];
__device__ __align__(16) unsigned char g_kidx [EE * 8];
__device__ __align__(16) ERec     g_rec   [EE];          // dst-sorted edge records
__device__ __align__(16) int      g_cnt   [NN];          // invariant: zero at replay start
__device__ __align__(16) int      g_ofs   [NN + 1];
__device__ __align__(16) int      g_pos   [NN];
// block-split hi/lo bf16 planes: per row, group of 8 values = [8 hi u16][8 lo u16]
__device__ __align__(16) unsigned g_acc2p [NN * KK * 32];
__device__ __align__(16) unsigned g_acc3p [(size_t)NN * KK * 64];
__device__ __align__(16) float    g_h1    [NN * 32];
__device__ __align__(16) float    g_h2    [NN * 64];
__device__ __align__(16) unsigned g_h1s   [NN * 32];     // block-split of g_h1
__device__ __align__(16) unsigned g_h2s   [NN * 64];     // block-split of g_h2
__device__ __align__(16) unsigned g_Bs2   [64  * (1536 + 32)];   // block-split B^T
__device__ __align__(16) unsigned g_Bs3   [128 * (3072 + 64)];

// ---------------- helpers ----------------
__device__ __forceinline__ uint32_t smem_u32(const void* p) {
    uint32_t a;
    asm("{ .reg .u64 t; cvta.to.shared.u64 t, %1; cvt.u32.u64 %0, t; }" : "=r"(a) : "l"(p));
    return a;
}
__device__ __forceinline__ unsigned short bfh(float v) {
    __nv_bfloat16 h = __float2bfloat16(v);
    union { __nv_bfloat16 b; unsigned short u; } c; c.b = h; return c.u;
}
__device__ __forceinline__ float bfhf(float v) {   // value of hi part
    return __bfloat162float(__float2bfloat16(v));
}
__device__ __forceinline__ void split8(const float* v, uint4& hb, uint4& lb) {
    unsigned h[4], l[4];
#pragma unroll
    for (int i = 0; i < 4; i++) {
        float a = v[i * 2], b = v[i * 2 + 1];
        h[i] = (unsigned)bfh(a) | ((unsigned)bfh(b) << 16);
        l[i] = (unsigned)bfh(a - bfhf(a)) | ((unsigned)bfh(b - bfhf(b)) << 16);
    }
    hb = make_uint4(h[0], h[1], h[2], h[3]);
    lb = make_uint4(l[0], l[1], l[2], l[3]);
}
__device__ __forceinline__ void mma16816(float* c, const unsigned* a, unsigned b0, unsigned b1) {
    asm volatile("mma.sync.aligned.m16n8k16.row.col.f32.bf16.bf16.f32 "
        "{%0,%1,%2,%3}, {%4,%5,%6,%7}, {%8,%9}, {%0,%1,%2,%3};"
        : "+f"(c[0]), "+f"(c[1]), "+f"(c[2]), "+f"(c[3])
        : "r"(a[0]), "r"(a[1]), "r"(a[2]), "r"(a[3]), "r"(b0), "r"(b1));
}
__device__ __forceinline__ void ldsm4(unsigned* r, uint32_t addr) {
    asm volatile("ldmatrix.sync.aligned.m8n8.x4.shared.b16 {%0,%1,%2,%3}, [%4];"
        : "=r"(r[0]), "=r"(r[1]), "=r"(r[2]), "=r"(r[3]) : "r"(addr));
}
__device__ __forceinline__ void cpa16(uint32_t dst, const void* src, int sz) {
    asm volatile("cp.async.cg.shared.global [%0], [%1], 16, %2;" :: "r"(dst), "l"(src), "r"(sz));
}
__device__ __forceinline__ void cpa16f(uint32_t dst, const void* src) {
    asm volatile("cp.async.cg.shared.global [%0], [%1], 16;" :: "r"(dst), "l"(src));
}

// ---------------- basis/kidx precompute + dst histogram (fused) ----------------
__global__ void precompute_kernel(const float* __restrict__ pseudo,
                                  const int* __restrict__ ei, int E) {
    int e = blockIdx.x * blockDim.x + threadIdx.x;
    if (e >= E) return;
    atomicAdd(&g_cnt[ei[E + e]], 1);
    float fr[3]; int lo[3];
    const int ksm1[3] = {2, 7, 1};
#pragma unroll
    for (int d = 0; d < 3; d++) {
        float u = pseudo[e * 3 + d] * (1.0f / 4.5f);
        u = fminf(fmaxf(u, 0.0f), 1.0f);
        float pos = u * (float)ksm1[d];
        float fl = floorf(pos);
        fr[d] = pos - fl;
        lo[d] = (int)fl;
    }
    float b[8]; unsigned char kx[8];
#pragma unroll
    for (int s = 0; s < 8; s++) {
        float w = 1.0f; int idx[3];
#pragma unroll
        for (int d = 0; d < 3; d++) {
            int bit = (s >> d) & 1;
            int id = lo[d] + bit;
            if (id > ksm1[d]) id = ksm1[d];
            idx[d] = id;
            w *= bit ? fr[d] : (1.0f - fr[d]);
        }
        b[s] = w;
        kx[s] = (unsigned char)(idx[0] * 16 + idx[1] * 2 + idx[2]);
    }
    *(float4*)&g_basis[e * 8]     = make_float4(b[0], b[1], b[2], b[3]);
    *(float4*)&g_basis[e * 8 + 4] = make_float4(b[4], b[5], b[6], b[7]);
    uchar4* kp = (uchar4*)&g_kidx[e * 8];
    kp[0] = make_uchar4(kx[0], kx[1], kx[2], kx[3]);
    kp[1] = make_uchar4(kx[4], kx[5], kx[6], kx[7]);
}

// fast single-block scan; also re-zeroes g_cnt for the next graph replay
__global__ void prefix_kernel() {
    constexpr int PER = (NN + 1023) / 1024;   // 20
    __shared__ int ws[32];
    int t = threadIdx.x;
    int base = t * PER;
    int loc[PER]; int sum = 0;
#pragma unroll
    for (int i = 0; i < PER; i++) {
        int idx = base + i;
        int v = 0;
        if (idx < NN) { v = g_cnt[idx]; g_cnt[idx] = 0; }
        loc[i] = sum; sum += v;
    }
    int x = sum;
#pragma unroll
    for (int o = 1; o < 32; o <<= 1) {
        int y = __shfl_up_sync(~0u, x, o);
        if ((t & 31) >= o) x += y;
    }
    if ((t & 31) == 31) ws[t >> 5] = x;
    __syncthreads();
    if (t < 32) {
        int w = ws[t];
#pragma unroll
        for (int o = 1; o < 32; o <<= 1) {
            int y = __shfl_up_sync(~0u, w, o);
            if (t >= o) w += y;
        }
        ws[t] = w;
    }
    __syncthreads();
    int ex = x - sum + ((t >= 32) ? ws[(t >> 5) - 1] : 0);
#pragma unroll
    for (int i = 0; i < PER; i++) {
        int idx = base + i;
        if (idx < NN) { g_ofs[idx] = ex + loc[i]; g_pos[idx] = ex + loc[i]; }
    }
    if (t == 1023) g_ofs[NN] = ex + sum;
}

__global__ void order_kernel(const int* __restrict__ ei, int E) {
    int e = blockIdx.x * blockDim.x + threadIdx.x;
    if (e >= E) return;
    int dst = ei[E + e];
    int p = atomicAdd(&g_pos[dst], 1);
    uint4 q0 = *(const uint4*)&g_basis[e * 8];
    uint4 q1 = *(const uint4*)&g_basis[e * 8 + 4];
    uint2 kv = *(const uint2*)&g_kidx[e * 8];
    uint4 q2 = make_uint4(kv.x, kv.y, (unsigned)ei[e], 0u);
    uint4* rp = (uint4*)&g_rec[p];
    rp[0] = q0; rp[1] = q1; rp[2] = q2;
}

// ---------------- weight transpose + block-split (8-group hi/lo) ----------------
template <int KA, int KH, int NC>
__global__ void bsplit_kernel(const float* __restrict__ W, const float* __restrict__ R) {
    constexpr int KT = KA + KH;
    unsigned* Bs = (KA == 1536) ? g_Bs2 : g_Bs3;
    int i = blockIdx.x * blockDim.x + threadIdx.x;
    if (i >= NC * (KT / 8)) return;
    int n = i / (KT / 8), g = i % (KT / 8);
    float v[8];
#pragma unroll
    for (int j = 0; j < 8; j++) {
        int k = g * 8 + j;
        v[j] = (k < KA) ? W[(size_t)k * NC + n] : R[(size_t)(k - KA) * NC + n];
    }
    uint4 hb, lb; split8(v, hb, lb);
    char* row = (char*)(Bs + (size_t)n * KT);
    *(uint4*)(row + g * 32)      = hb;
    *(uint4*)(row + g * 32 + 16) = lb;
}

// ---------------- fused layer-1: bucket gather + dense + relu + hi/lo split ----------------
__global__ void __launch_bounds__(128) layer1_kernel(const float* __restrict__ x,
                                                     const float* __restrict__ W1,
                                                     const float* __restrict__ root1,
                                                     const float* __restrict__ b1, int N) {
    __shared__ float buck[4][KK];
    __shared__ float hrow[4][32];
    int wi = threadIdx.x >> 5, o = threadIdx.x & 31;
    int n = blockIdx.x * 4 + wi;
    if (n >= N) return;
    float* bk = buck[wi];
#pragma unroll
    for (int k = o; k < KK; k += 32) bk[k] = 0.0f;
    __syncwarp();
    int beg = g_ofs[n], end = g_ofs[n + 1];
    for (int i = beg + o; i < end; i += 32) {
        const uint4* rp = (const uint4*)&g_rec[i];
        uint4 q0 = rp[0], q1 = rp[1], q2 = rp[2];
        float xs = __ldg(&x[(int)q2.z]);
        atomicAdd(&bk[(q2.x      ) & 0xff], __uint_as_float(q0.x) * xs);
        atomicAdd(&bk[(q2.x >>  8) & 0xff], __uint_as_float(q0.y) * xs);
        atomicAdd(&bk[(q2.x >> 16) & 0xff], __uint_as_float(q0.z) * xs);
        atomicAdd(&bk[(q2.x >> 24)       ], __uint_as_float(q0.w) * xs);
        atomicAdd(&bk[(q2.y      ) & 0xff], __uint_as_float(q1.x) * xs);
        atomicAdd(&bk[(q2.y >>  8) & 0xff], __uint_as_float(q1.y) * xs);
        atomicAdd(&bk[(q2.y >> 16) & 0xff], __uint_as_float(q1.z) * xs);
        atomicAdd(&bk[(q2.y >> 24)       ], __uint_as_float(q1.w) * xs);
    }
    __syncwarp();
    float s = x[n] * __ldg(&root1[o]) + __ldg(&b1[o]);
#pragma unroll
    for (int k = 0; k < KK; k++) s += bk[k] * __ldg(&W1[k * 32 + o]);
    s = fmaxf(s, 0.0f);
    g_h1[n * 32 + o] = s;
    hrow[wi][o] = s;
    __syncwarp();
    if (o < 16) {
        float a = hrow[wi][o * 2], b = hrow[wi][o * 2 + 1];
        unsigned hi = (unsigned)bfh(a) | ((unsigned)bfh(b) << 16);
        unsigned lo = (unsigned)bfh(a - bfhf(a)) | ((unsigned)bfh(b - bfhf(b)) << 16);
        char* row = (char*)(g_h1s + (size_t)n * 32);
        int byte = (o >> 2) * 32 + (o & 3) * 4;
        *(unsigned*)(row + byte)      = hi;
        *(unsigned*)(row + byte + 16) = lo;
    }
}

// ---------------- gather_scatter, warp-per-node, VEC channels/thread ----------------
// CIN=32: VEC=1 (lane=channel).  CIN=64: VEC=2 (lane -> channels 2l,2l+1).
// 4 nodes per 128-thread CTA; 2-deep software prefetch of (record, h).
template <int CIN>
__global__ void __launch_bounds__(128) gather_scatter_kernel(int N) {
    constexpr int VEC = CIN / 32;
    const float* __restrict__ h = (CIN == 32) ? g_h1 : g_h2;
    unsigned* __restrict__ accP = (CIN == 32) ? g_acc2p : g_acc3p;
    __shared__ float buck[4][KK * CIN];
    int wi = threadIdx.x >> 5, lane = threadIdx.x & 31;
    int n = blockIdx.x * 4 + wi;
    if (n >= N) return;
    float* bk = buck[wi];
#pragma unroll
    for (int i = lane; i < KK * CIN / 4; i += 32) ((float4*)bk)[i] = make_float4(0.f, 0.f, 0.f, 0.f);
    __syncwarp();

    int beg = g_ofs[n], end = g_ofs[n + 1];
    int cnt = end - beg;
    uint4 Ar0, Ar1, Ar2, Br0, Br1, Br2;
    float2 hA, hB;
    auto ldrec = [&](int i, uint4& r0, uint4& r1, uint4& r2) {
        const uint4* rp = (const uint4*)&g_rec[i];
        r0 = rp[0]; r1 = rp[1]; r2 = rp[2];
    };
    auto ldh = [&](const uint4& r2) -> float2 {
        const float* hp = h + (size_t)(int)r2.z * CIN + lane * VEC;
        if (VEC == 2) return *(const float2*)hp;
        return make_float2(__ldg(hp), 0.0f);
    };
    if (cnt > 0) { ldrec(beg, Ar0, Ar1, Ar2); hA = ldh(Ar2); }
    if (cnt > 1) { ldrec(beg + 1, Br0, Br1, Br2); hB = ldh(Br2); }
    for (int i = 0; i < cnt; i++) {
        uint4 Cr0, Cr1, Cr2;
        if (i + 2 < cnt) ldrec(beg + i + 2, Cr0, Cr1, Cr2);
        {
            float bs[8] = {__uint_as_float(Ar0.x), __uint_as_float(Ar0.y),
                           __uint_as_float(Ar0.z), __uint_as_float(Ar0.w),
                           __uint_as_float(Ar1.x), __uint_as_float(Ar1.y),
                           __uint_as_float(Ar1.z), __uint_as_float(Ar1.w)};
            unsigned kx[8] = {(Ar2.x) & 0xff, (Ar2.x >> 8) & 0xff, (Ar2.x >> 16) & 0xff, (Ar2.x >> 24),
                              (Ar2.y) & 0xff, (Ar2.y >> 8) & 0xff, (Ar2.y >> 16) & 0xff, (Ar2.y >> 24)};
#pragma unroll
            for (int s = 0; s < 8; s++) {
                float* p = &bk[kx[s] * CIN + lane * VEC];
                if (VEC == 2) {
                    float2 v = *(float2*)p;
                    v.x += bs[s] * hA.x;
                    v.y += bs[s] * hA.y;
                    *(float2*)p = v;
                } else {
                    p[0] += bs[s] * hA.x;
                }
            }
        }
        Ar0 = Br0; Ar1 = Br1; Ar2 = Br2; hA = hB;
        Br0 = Cr0; Br1 = Cr1; Br2 = Cr2;
        if (i + 2 < cnt) hB = ldh(Br2);
    }
    __syncwarp();
    // write block-split row: group g = 8 consecutive flat (k,ch) values
    char* row = (char*)(accP + (size_t)n * KK * CIN);
    constexpr int NG = KK * CIN / 8;
#pragma unroll
    for (int g = lane; g < NG; g += 32) {
        float v[8];
#pragma unroll
        for (int j = 0; j < 8; j++) v[j] = bk[g * 8 + j];
        uint4 hb, lb; split8(v, hb, lb);
        *(uint4*)(row + g * 32)      = hb;
        *(uint4*)(row + g * 32 + 16) = lb;
    }
}

// ---------------- cp.async bf16-split GEMM (4-stage); gemm3 fuses log_softmax ----------------
template <int KA, int KH, int BN>
__global__ void __launch_bounds__(256) gemm_cp_kernel(const float* __restrict__ bias,
                                                      float* __restrict__ Cout, int M) {
    constexpr int KT = KA + KH;
    constexpr int CHA = KA / 32, CH = KT / 32;
    constexpr int BM = 64;
    constexpr int ASZ = BM * 128, BSZ = BN * 128, STAGE = ASZ + BSZ;
    constexpr int NTP = BN / 64;
    constexpr bool FUSE_LSM = (KA == 3072);
    extern __shared__ __align__(16) char dsm[];
    const uint32_t sb = smem_u32(dsm);

    const unsigned* Ag = (KA == 1536) ? g_acc2p : g_acc3p;
    const unsigned* Hg = (KA == 1536) ? g_h1s : g_h2s;
    const unsigned* Bg = (KA == 1536) ? g_Bs2 : g_Bs3;
    float* C = (KA == 1536) ? g_h2 : Cout;

    const int t = threadIdx.x, wid = t >> 5, lane = t & 31;
    const int wm = wid & 1, wn = wid >> 1;
    const int m0 = blockIdx.x * BM;
    const int lr = lane & 15, lh = lane >> 4;

    auto issue = [&](int c) {
        int buf = c & 3;
        uint32_t sA = sb + buf * STAGE, sB = sA + ASZ;
        const char* gA; size_t strA;
        if (c < CHA) { gA = (const char*)Ag + (size_t)c * 128;        strA = (size_t)KA * 4; }
        else         { gA = (const char*)Hg + (size_t)(c - CHA) * 128; strA = (size_t)KH * 4; }
#pragma unroll
        for (int j = 0; j < 2; j++) {
            int slot = j * 256 + t;
            int r = slot >> 3, s = slot & 7;
            int gr = m0 + r;
            cpa16(sA + r * 128 + ((s ^ (r & 7)) * 16),
                  gA + (size_t)gr * strA + s * 16, (gr < M) ? 16 : 0);
        }
        const char* gB = (const char*)Bg + (size_t)c * 128;
#pragma unroll
        for (int j = 0; j < BN / 32; j++) {
            int slot = j * 256 + t;
            int r = slot >> 3, s = slot & 7;
            cpa16f(sB + r * 128 + ((s ^ (r & 7)) * 16),
                   gB + (size_t)r * ((size_t)KT * 4) + s * 16);
        }
        asm volatile("cp.async.commit_group;" ::: "memory");
    };

    float cacc[2][NTP * 2][4];
#pragma unroll
    for (int i = 0; i < 2; i++)
#pragma unroll
        for (int j = 0; j < NTP * 2; j++)
#pragma unroll
            for (int q = 0; q < 4; q++) cacc[i][j][q] = 0.0f;

    issue(0);
    if (1 < CH) issue(1);
    if (2 < CH) issue(2);
    for (int c = 0; c < CH; c++) {
        if (c + 3 < CH) {
            issue(c + 3);
            asm volatile("cp.async.wait_group 3;" ::: "memory");
        } else {
            asm volatile("cp.async.wait_group 0;" ::: "memory");
        }
        __syncthreads();

        uint32_t sA = sb + (c & 3) * STAGE, sB = sA + ASZ;
#pragma unroll
        for (int ks = 0; ks < 2; ks++) {
            int sg = 4 * ks + 2 * lh;
            unsigned ah[2][4], al[2][4];
#pragma unroll
            for (int mt = 0; mt < 2; mt++) {
                int r = wm * 32 + mt * 16 + lr;
                ldsm4(ah[mt], sA + r * 128 + ((sg ^ (r & 7)) * 16));
                ldsm4(al[mt], sA + r * 128 + (((sg + 1) ^ (r & 7)) * 16));
            }
#pragma unroll
            for (int ntp = 0; ntp < NTP; ntp++) {
                unsigned bh[4], bl[4];
                int rn = wn * (BN / 4) + ntp * 16 + lr;
                ldsm4(bh, sB + rn * 128 + ((sg ^ (rn & 7)) * 16));
                ldsm4(bl, sB + rn * 128 + (((sg + 1) ^ (rn & 7)) * 16));
#pragma unroll
                for (int mt = 0; mt < 2; mt++) {
#pragma unroll
                    for (int ns = 0; ns < 2; ns++) {
                        float* cf = cacc[mt][ntp * 2 + ns];
                        mma16816(cf, ah[mt], bh[ns], bh[ns + 2]);
                        mma16816(cf, ah[mt], bl[ns], bl[ns + 2]);
                        mma16816(cf, al[mt], bh[ns], bh[ns + 2]);
                    }
                }
            }
        }
        __syncthreads();
    }

    float* s_out = (float*)dsm;    // reuse pipeline smem: [BM][BN] relu'd tile
    auto emit = [&](int row, int col, float vx, float vy) {
        if (row >= M) return;
        if constexpr (FUSE_LSM) {
            s_out[(row - m0) * BN + col] = vx;
            s_out[(row - m0) * BN + col + 1] = vy;
        } else {
            float2 o; o.x = vx; o.y = vy;
            *(float2*)(C + (size_t)row * BN + col) = o;
            unsigned hi = (unsigned)bfh(vx) | ((unsigned)bfh(vy) << 16);
            unsigned lo = (unsigned)bfh(vx - bfhf(vx)) | ((unsigned)bfh(vy - bfhf(vy)) << 16);
            char* rp = (char*)(g_h2s + (size_t)row * 64);
            int byte = (col >> 3) * 32 + (col & 7) * 2;
            *(unsigned*)(rp + byte)      = hi;
            *(unsigned*)(rp + byte + 16) = lo;
        }
    };
#pragma unroll
    for (int mt = 0; mt < 2; mt++) {
#pragma unroll
        for (int j = 0; j < NTP * 2; j++) {
            int row = m0 + wm * 32 + mt * 16 + (lane >> 2);
            int col = wn * (BN / 4) + (j >> 1) * 16 + (j & 1) * 8 + (lane & 3) * 2;
            float bx = __ldg(&bias[col]), by = __ldg(&bias[col + 1]);
            emit(row, col, fmaxf(cacc[mt][j][0] + bx, 0.0f), fmaxf(cacc[mt][j][1] + by, 0.0f));
            emit(row + 8, col, fmaxf(cacc[mt][j][2] + bx, 0.0f), fmaxf(cacc[mt][j][3] + by, 0.0f));
        }
    }

    if constexpr (FUSE_LSM) {
        __syncthreads();
        // warp wid handles rows [8*wid, 8*wid+8); 128 cols -> 4 vals/lane
#pragma unroll
        for (int r8 = 0; r8 < 8; r8++) {
            int rl = wid * 8 + r8;
            int gr = m0 + rl;
            if (gr >= M) break;
            float v[4];
#pragma unroll
            for (int j = 0; j < 4; j++) v[j] = s_out[rl * 128 + lane + 32 * j];
            float mx = fmaxf(fmaxf(v[0], v[1]), fmaxf(v[2], v[3]));
#pragma unroll
            for (int o = 16; o > 0; o >>= 1) mx = fmaxf(mx, __shfl_xor_sync(~0u, mx, o));
            float s = 0.0f;
#pragma unroll
            for (int j = 0; j < 4; j++) s += expf(v[j] - mx);
#pragma unroll
            for (int o = 16; o > 0; o >>= 1) s += __shfl_xor_sync(~0u, s, o);
            float lse = mx + logf(s);
#pragma unroll
            for (int j = 0; j < 4; j++)
                Cout[(size_t)gr * 128 + lane + 32 * j] = v[j] - lse;
        }
    }
}

// ---------------- entry ----------------
extern "C" void kernel_launch(void* const* d_in, const int* in_sizes, int n_in,
                              void* d_out, int out_size) {
    const float* x      = (const float*)d_in[0];
    const int*   ei     = (const int*)  d_in[1];
    const float* pseudo = (const float*)d_in[2];
    const float* W1     = (const float*)d_in[3];
    const float* root1  = (const float*)d_in[4];
    const float* b1     = (const float*)d_in[5];
    const float* W2     = (const float*)d_in[6];
    const float* root2  = (const float*)d_in[7];
    const float* b2     = (const float*)d_in[8];
    const float* W3     = (const float*)d_in[9];
    const float* root3  = (const float*)d_in[10];
    const float* b3     = (const float*)d_in[11];
    float* out = (float*)d_out;
    int N = in_sizes[0];
    int E = in_sizes[1] / 2;

    const int SMEM2 = 4 * (64 * 128 + 64 * 128);    // 65536
    const int SMEM3 = 4 * (64 * 128 + 128 * 128);   // 98304
    cudaFuncSetAttribute(gemm_cp_kernel<1536, 32, 64>,
                         cudaFuncAttributeMaxDynamicSharedMemorySize, SMEM2);
    cudaFuncSetAttribute(gemm_cp_kernel<3072, 64, 128>,
                         cudaFuncAttributeMaxDynamicSharedMemorySize, SMEM3);

    int eb = (E + 255) / 256;
    int nb4 = (N + 3) / 4;
    precompute_kernel<<<eb, 256>>>(pseudo, ei, E);       // basis + hist (fused)
    prefix_kernel<<<1, 1024>>>();                        // scan + re-zero g_cnt
    order_kernel<<<eb, 256>>>(ei, E);
    layer1_kernel<<<nb4, 128>>>(x, W1, root1, b1, N);
    bsplit_kernel<1536, 32, 64><<<(64 * 196 + 255) / 256, 256>>>(W2, root2);
    bsplit_kernel<3072, 64, 128><<<(128 * 392 + 255) / 256, 256>>>(W3, root3);
    gather_scatter_kernel<32><<<nb4, 128>>>(N);
    gemm_cp_kernel<1536, 32, 64><<<(N + 63) / 64, 256, SMEM2>>>(b2, nullptr, N);
    gather_scatter_kernel<64><<<nb4, 128>>>(N);
    gemm_cp_kernel<3072, 64, 128><<<(N + 63) / 64, 256, SMEM3>>>(b3, out, N);
}

// round 16
// speedup vs baseline: 1.5249x; 1.5249x over previous
#include <cuda_runtime.h>
#include <cuda_bf16.h>
#include <cstdint>

#define NN 20000
#define EE 500000
#define KK 48

// ---------------- device scratch (no allocations allowed) ----------------
struct __align__(16) ERec { float b[8]; unsigned kx[2]; int src; int pad; };  // 48B

__device__ __align__(16) float    g_basis [EE * 8];
__device__ __align__(16) unsigned char g_kidx [EE * 8];
__device__ __align__(16) ERec     g_rec   [EE];          // dst-sorted edge records
__device__ __align__(16) int      g_cnt   [NN];          // invariant: zero at replay start
__device__ __align__(16) int      g_ofs   [NN + 1];
__device__ __align__(16) int      g_pos   [NN];
// block-split hi/lo bf16 planes: per row, group of 8 values = [8 hi u16][8 lo u16]
__device__ __align__(16) unsigned g_acc2p [NN * KK * 32];
__device__ __align__(16) unsigned g_acc3p [(size_t)NN * KK * 64];
__device__ __align__(16) float    g_h1    [NN * 32];
__device__ __align__(16) float    g_h2    [NN * 64];
__device__ __align__(16) unsigned g_h1s   [NN * 32];     // block-split of g_h1
__device__ __align__(16) unsigned g_h2s   [NN * 64];     // block-split of g_h2
__device__ __align__(16) unsigned g_Bs2   [64  * (1536 + 32)];   // block-split B^T
__device__ __align__(16) unsigned g_Bs3   [128 * (3072 + 64)];

// ---------------- helpers ----------------
__device__ __forceinline__ uint32_t smem_u32(const void* p) {
    uint32_t a;
    asm("{ .reg .u64 t; cvta.to.shared.u64 t, %1; cvt.u32.u64 %0, t; }" : "=r"(a) : "l"(p));
    return a;
}
__device__ __forceinline__ unsigned short bfh(float v) {
    __nv_bfloat16 h = __float2bfloat16(v);
    union { __nv_bfloat16 b; unsigned short u; } c; c.b = h; return c.u;
}
__device__ __forceinline__ float bfhf(float v) {   // value of hi part
    return __bfloat162float(__float2bfloat16(v));
}
__device__ __forceinline__ void split8(const float* v, uint4& hb, uint4& lb) {
    unsigned h[4], l[4];
#pragma unroll
    for (int i = 0; i < 4; i++) {
        float a = v[i * 2], b = v[i * 2 + 1];
        h[i] = (unsigned)bfh(a) | ((unsigned)bfh(b) << 16);
        l[i] = (unsigned)bfh(a - bfhf(a)) | ((unsigned)bfh(b - bfhf(b)) << 16);
    }
    hb = make_uint4(h[0], h[1], h[2], h[3]);
    lb = make_uint4(l[0], l[1], l[2], l[3]);
}
__device__ __forceinline__ void mma16816(float* c, const unsigned* a, unsigned b0, unsigned b1) {
    asm volatile("mma.sync.aligned.m16n8k16.row.col.f32.bf16.bf16.f32 "
        "{%0,%1,%2,%3}, {%4,%5,%6,%7}, {%8,%9}, {%0,%1,%2,%3};"
        : "+f"(c[0]), "+f"(c[1]), "+f"(c[2]), "+f"(c[3])
        : "r"(a[0]), "r"(a[1]), "r"(a[2]), "r"(a[3]), "r"(b0), "r"(b1));
}
__device__ __forceinline__ void ldsm4(unsigned* r, uint32_t addr) {
    asm volatile("ldmatrix.sync.aligned.m8n8.x4.shared.b16 {%0,%1,%2,%3}, [%4];"
        : "=r"(r[0]), "=r"(r[1]), "=r"(r[2]), "=r"(r[3]) : "r"(addr));
}
__device__ __forceinline__ void cpa16(uint32_t dst, const void* src, int sz) {
    asm volatile("cp.async.cg.shared.global [%0], [%1], 16, %2;" :: "r"(dst), "l"(src), "r"(sz));
}
__device__ __forceinline__ void cpa16f(uint32_t dst, const void* src) {
    asm volatile("cp.async.cg.shared.global [%0], [%1], 16;" :: "r"(dst), "l"(src));
}

// ---------------- basis/kidx precompute + dst histogram (fused) ----------------
__global__ void precompute_kernel(const float* __restrict__ pseudo,
                                  const int* __restrict__ ei, int E) {
    int e = blockIdx.x * blockDim.x + threadIdx.x;
    if (e >= E) return;
    atomicAdd(&g_cnt[ei[E + e]], 1);
    float fr[3]; int lo[3];
    const int ksm1[3] = {2, 7, 1};
#pragma unroll
    for (int d = 0; d < 3; d++) {
        float u = pseudo[e * 3 + d] * (1.0f / 4.5f);
        u = fminf(fmaxf(u, 0.0f), 1.0f);
        float pos = u * (float)ksm1[d];
        float fl = floorf(pos);
        fr[d] = pos - fl;
        lo[d] = (int)fl;
    }
    float b[8]; unsigned char kx[8];
#pragma unroll
    for (int s = 0; s < 8; s++) {
        float w = 1.0f; int idx[3];
#pragma unroll
        for (int d = 0; d < 3; d++) {
            int bit = (s >> d) & 1;
            int id = lo[d] + bit;
            if (id > ksm1[d]) id = ksm1[d];
            idx[d] = id;
            w *= bit ? fr[d] : (1.0f - fr[d]);
        }
        b[s] = w;
        kx[s] = (unsigned char)(idx[0] * 16 + idx[1] * 2 + idx[2]);
    }
    *(float4*)&g_basis[e * 8]     = make_float4(b[0], b[1], b[2], b[3]);
    *(float4*)&g_basis[e * 8 + 4] = make_float4(b[4], b[5], b[6], b[7]);
    uchar4* kp = (uchar4*)&g_kidx[e * 8];
    kp[0] = make_uchar4(kx[0], kx[1], kx[2], kx[3]);
    kp[1] = make_uchar4(kx[4], kx[5], kx[6], kx[7]);
}

// fast single-block scan; also re-zeroes g_cnt for the next graph replay
__global__ void prefix_kernel() {
    constexpr int PER = (NN + 1023) / 1024;   // 20
    __shared__ int ws[32];
    int t = threadIdx.x;
    int base = t * PER;
    int loc[PER]; int sum = 0;
#pragma unroll
    for (int i = 0; i < PER; i++) {
        int idx = base + i;
        int v = 0;
        if (idx < NN) { v = g_cnt[idx]; g_cnt[idx] = 0; }
        loc[i] = sum; sum += v;
    }
    int x = sum;
#pragma unroll
    for (int o = 1; o < 32; o <<= 1) {
        int y = __shfl_up_sync(~0u, x, o);
        if ((t & 31) >= o) x += y;
    }
    if ((t & 31) == 31) ws[t >> 5] = x;
    __syncthreads();
    if (t < 32) {
        int w = ws[t];
#pragma unroll
        for (int o = 1; o < 32; o <<= 1) {
            int y = __shfl_up_sync(~0u, w, o);
            if (t >= o) w += y;
        }
        ws[t] = w;
    }
    __syncthreads();
    int ex = x - sum + ((t >= 32) ? ws[(t >> 5) - 1] : 0);
#pragma unroll
    for (int i = 0; i < PER; i++) {
        int idx = base + i;
        if (idx < NN) { g_ofs[idx] = ex + loc[i]; g_pos[idx] = ex + loc[i]; }
    }
    if (t == 1023) g_ofs[NN] = ex + sum;
}

__global__ void order_kernel(const int* __restrict__ ei, int E) {
    int e = blockIdx.x * blockDim.x + threadIdx.x;
    if (e >= E) return;
    int dst = ei[E + e];
    int p = atomicAdd(&g_pos[dst], 1);
    uint4 q0 = *(const uint4*)&g_basis[e * 8];
    uint4 q1 = *(const uint4*)&g_basis[e * 8 + 4];
    uint2 kv = *(const uint2*)&g_kidx[e * 8];
    uint4 q2 = make_uint4(kv.x, kv.y, (unsigned)ei[e], 0u);
    uint4* rp = (uint4*)&g_rec[p];
    rp[0] = q0; rp[1] = q1; rp[2] = q2;
}

// ---------------- weight transpose + block-split (8-group hi/lo) ----------------
template <int KA, int KH, int NC>
__global__ void bsplit_kernel(const float* __restrict__ W, const float* __restrict__ R) {
    constexpr int KT = KA + KH;
    unsigned* Bs = (KA == 1536) ? g_Bs2 : g_Bs3;
    int i = blockIdx.x * blockDim.x + threadIdx.x;
    if (i >= NC * (KT / 8)) return;
    int n = i / (KT / 8), g = i % (KT / 8);
    float v[8];
#pragma unroll
    for (int j = 0; j < 8; j++) {
        int k = g * 8 + j;
        v[j] = (k < KA) ? W[(size_t)k * NC + n] : R[(size_t)(k - KA) * NC + n];
    }
    uint4 hb, lb; split8(v, hb, lb);
    char* row = (char*)(Bs + (size_t)n * KT);
    *(uint4*)(row + g * 32)      = hb;
    *(uint4*)(row + g * 32 + 16) = lb;
}

// ---------------- fused layer-1: bucket gather + dense + relu + hi/lo split ----------------
__global__ void __launch_bounds__(128) layer1_kernel(const float* __restrict__ x,
                                                     const float* __restrict__ W1,
                                                     const float* __restrict__ root1,
                                                     const float* __restrict__ b1, int N) {
    __shared__ float buck[4][KK];
    __shared__ float hrow[4][32];
    int wi = threadIdx.x >> 5, o = threadIdx.x & 31;
    int n = blockIdx.x * 4 + wi;
    if (n >= N) return;
    float* bk = buck[wi];
#pragma unroll
    for (int k = o; k < KK; k += 32) bk[k] = 0.0f;
    __syncwarp();
    int beg = g_ofs[n], end = g_ofs[n + 1];
    for (int i = beg + o; i < end; i += 32) {
        const uint4* rp = (const uint4*)&g_rec[i];
        uint4 q0 = rp[0], q1 = rp[1], q2 = rp[2];
        float xs = __ldg(&x[(int)q2.z]);
        atomicAdd(&bk[(q2.x      ) & 0xff], __uint_as_float(q0.x) * xs);
        atomicAdd(&bk[(q2.x >>  8) & 0xff], __uint_as_float(q0.y) * xs);
        atomicAdd(&bk[(q2.x >> 16) & 0xff], __uint_as_float(q0.z) * xs);
        atomicAdd(&bk[(q2.x >> 24)       ], __uint_as_float(q0.w) * xs);
        atomicAdd(&bk[(q2.y      ) & 0xff], __uint_as_float(q1.x) * xs);
        atomicAdd(&bk[(q2.y >>  8) & 0xff], __uint_as_float(q1.y) * xs);
        atomicAdd(&bk[(q2.y >> 16) & 0xff], __uint_as_float(q1.z) * xs);
        atomicAdd(&bk[(q2.y >> 24)       ], __uint_as_float(q1.w) * xs);
    }
    __syncwarp();
    float s = x[n] * __ldg(&root1[o]) + __ldg(&b1[o]);
#pragma unroll
    for (int k = 0; k < KK; k++) s += bk[k] * __ldg(&W1[k * 32 + o]);
    s = fmaxf(s, 0.0f);
    g_h1[n * 32 + o] = s;
    hrow[wi][o] = s;
    __syncwarp();
    if (o < 16) {
        float a = hrow[wi][o * 2], b = hrow[wi][o * 2 + 1];
        unsigned hi = (unsigned)bfh(a) | ((unsigned)bfh(b) << 16);
        unsigned lo = (unsigned)bfh(a - bfhf(a)) | ((unsigned)bfh(b - bfhf(b)) << 16);
        char* row = (char*)(g_h1s + (size_t)n * 32);
        int byte = (o >> 2) * 32 + (o & 3) * 4;
        *(unsigned*)(row + byte)      = hi;
        *(unsigned*)(row + byte + 16) = lo;
    }
}

// ---------------- gather_scatter, warp-per-node, VEC channels/thread ----------------
// CIN=32: VEC=1 (lane=channel).  CIN=64: VEC=2 (lane -> channels 2l,2l+1).
// 4 nodes per 128-thread CTA; 2-deep software prefetch of (record, h).
template <int CIN>
__global__ void __launch_bounds__(128) gather_scatter_kernel(int N) {
    constexpr int VEC = CIN / 32;
    const float* __restrict__ h = (CIN == 32) ? g_h1 : g_h2;
    unsigned* __restrict__ accP = (CIN == 32) ? g_acc2p : g_acc3p;
    __shared__ float buck[4][KK * CIN];
    int wi = threadIdx.x >> 5, lane = threadIdx.x & 31;
    int n = blockIdx.x * 4 + wi;
    if (n >= N) return;
    float* bk = buck[wi];
#pragma unroll
    for (int i = lane; i < KK * CIN / 4; i += 32) ((float4*)bk)[i] = make_float4(0.f, 0.f, 0.f, 0.f);
    __syncwarp();

    int beg = g_ofs[n], end = g_ofs[n + 1];
    int cnt = end - beg;
    uint4 Ar0, Ar1, Ar2, Br0, Br1, Br2;
    float2 hA, hB;
    auto ldrec = [&](int i, uint4& r0, uint4& r1, uint4& r2) {
        const uint4* rp = (const uint4*)&g_rec[i];
        r0 = rp[0]; r1 = rp[1]; r2 = rp[2];
    };
    auto ldh = [&](const uint4& r2) -> float2 {
        const float* hp = h + (size_t)(int)r2.z * CIN + lane * VEC;
        if (VEC == 2) return *(const float2*)hp;
        return make_float2(__ldg(hp), 0.0f);
    };
    if (cnt > 0) { ldrec(beg, Ar0, Ar1, Ar2); hA = ldh(Ar2); }
    if (cnt > 1) { ldrec(beg + 1, Br0, Br1, Br2); hB = ldh(Br2); }
    for (int i = 0; i < cnt; i++) {
        uint4 Cr0, Cr1, Cr2;
        if (i + 2 < cnt) ldrec(beg + i + 2, Cr0, Cr1, Cr2);
        {
            float bs[8] = {__uint_as_float(Ar0.x), __uint_as_float(Ar0.y),
                           __uint_as_float(Ar0.z), __uint_as_float(Ar0.w),
                           __uint_as_float(Ar1.x), __uint_as_float(Ar1.y),
                           __uint_as_float(Ar1.z), __uint_as_float(Ar1.w)};
            unsigned kx[8] = {(Ar2.x) & 0xff, (Ar2.x >> 8) & 0xff, (Ar2.x >> 16) & 0xff, (Ar2.x >> 24),
                              (Ar2.y) & 0xff, (Ar2.y >> 8) & 0xff, (Ar2.y >> 16) & 0xff, (Ar2.y >> 24)};
#pragma unroll
            for (int s = 0; s < 8; s++) {
                float* p = &bk[kx[s] * CIN + lane * VEC];
                if (VEC == 2) {
                    float2 v = *(float2*)p;
                    v.x += bs[s] * hA.x;
                    v.y += bs[s] * hA.y;
                    *(float2*)p = v;
                } else {
                    p[0] += bs[s] * hA.x;
                }
            }
        }
        Ar0 = Br0; Ar1 = Br1; Ar2 = Br2; hA = hB;
        Br0 = Cr0; Br1 = Cr1; Br2 = Cr2;
        if (i + 2 < cnt) hB = ldh(Br2);
    }
    __syncwarp();
    // write block-split row: group g = 8 consecutive flat (k,ch) values
    char* row = (char*)(accP + (size_t)n * KK * CIN);
    constexpr int NG = KK * CIN / 8;
#pragma unroll
    for (int g = lane; g < NG; g += 32) {
        float v[8];
#pragma unroll
        for (int j = 0; j < 8; j++) v[j] = bk[g * 8 + j];
        uint4 hb, lb; split8(v, hb, lb);
        *(uint4*)(row + g * 32)      = hb;
        *(uint4*)(row + g * 32 + 16) = lb;
    }
}

// ---------------- cp.async bf16-split GEMM (4-stage); gemm3 fuses log_softmax ----------------
template <int KA, int KH, int BN>
__global__ void __launch_bounds__(256) gemm_cp_kernel(const float* __restrict__ bias,
                                                      float* __restrict__ Cout, int M) {
    constexpr int KT = KA + KH;
    constexpr int CHA = KA / 32, CH = KT / 32;
    constexpr int BM = 64;
    constexpr int ASZ = BM * 128, BSZ = BN * 128, STAGE = ASZ + BSZ;
    constexpr int NTP = BN / 64;
    constexpr bool FUSE_LSM = (KA == 3072);
    extern __shared__ __align__(16) char dsm[];
    const uint32_t sb = smem_u32(dsm);

    const unsigned* Ag = (KA == 1536) ? g_acc2p : g_acc3p;
    const unsigned* Hg = (KA == 1536) ? g_h1s : g_h2s;
    const unsigned* Bg = (KA == 1536) ? g_Bs2 : g_Bs3;
    float* C = (KA == 1536) ? g_h2 : Cout;

    const int t = threadIdx.x, wid = t >> 5, lane = t & 31;
    const int wm = wid & 1, wn = wid >> 1;
    const int m0 = blockIdx.x * BM;
    const int lr = lane & 15, lh = lane >> 4;

    auto issue = [&](int c) {
        int buf = c & 3;
        uint32_t sA = sb + buf * STAGE, sB = sA + ASZ;
        const char* gA; size_t strA;
        if (c < CHA) { gA = (const char*)Ag + (size_t)c * 128;        strA = (size_t)KA * 4; }
        else         { gA = (const char*)Hg + (size_t)(c - CHA) * 128; strA = (size_t)KH * 4; }
#pragma unroll
        for (int j = 0; j < 2; j++) {
            int slot = j * 256 + t;
            int r = slot >> 3, s = slot & 7;
            int gr = m0 + r;
            cpa16(sA + r * 128 + ((s ^ (r & 7)) * 16),
                  gA + (size_t)gr * strA + s * 16, (gr < M) ? 16 : 0);
        }
        const char* gB = (const char*)Bg + (size_t)c * 128;
#pragma unroll
        for (int j = 0; j < BN / 32; j++) {
            int slot = j * 256 + t;
            int r = slot >> 3, s = slot & 7;
            cpa16f(sB + r * 128 + ((s ^ (r & 7)) * 16),
                   gB + (size_t)r * ((size_t)KT * 4) + s * 16);
        }
        asm volatile("cp.async.commit_group;" ::: "memory");
    };

    float cacc[2][NTP * 2][4];
#pragma unroll
    for (int i = 0; i < 2; i++)
#pragma unroll
        for (int j = 0; j < NTP * 2; j++)
#pragma unroll
            for (int q = 0; q < 4; q++) cacc[i][j][q] = 0.0f;

    issue(0);
    if (1 < CH) issue(1);
    if (2 < CH) issue(2);
    for (int c = 0; c < CH; c++) {
        if (c + 3 < CH) {
            issue(c + 3);
            asm volatile("cp.async.wait_group 3;" ::: "memory");
        } else {
            asm volatile("cp.async.wait_group 0;" ::: "memory");
        }
        __syncthreads();

        uint32_t sA = sb + (c & 3) * STAGE, sB = sA + ASZ;
#pragma unroll
        for (int ks = 0; ks < 2; ks++) {
            int sg = 4 * ks + 2 * lh;
            unsigned ah[2][4], al[2][4];
#pragma unroll
            for (int mt = 0; mt < 2; mt++) {
                int r = wm * 32 + mt * 16 + lr;
                ldsm4(ah[mt], sA + r * 128 + ((sg ^ (r & 7)) * 16));
                ldsm4(al[mt], sA + r * 128 + (((sg + 1) ^ (r & 7)) * 16));
            }
#pragma unroll
            for (int ntp = 0; ntp < NTP; ntp++) {
                unsigned bh[4], bl[4];
                int rn = wn * (BN / 4) + ntp * 16 + lr;
                ldsm4(bh, sB + rn * 128 + ((sg ^ (rn & 7)) * 16));
                ldsm4(bl, sB + rn * 128 + (((sg + 1) ^ (rn & 7)) * 16));
#pragma unroll
                for (int mt = 0; mt < 2; mt++) {
#pragma unroll
                    for (int ns = 0; ns < 2; ns++) {
                        float* cf = cacc[mt][ntp * 2 + ns];
                        mma16816(cf, ah[mt], bh[ns], bh[ns + 2]);
                        mma16816(cf, ah[mt], bl[ns], bl[ns + 2]);
                        mma16816(cf, al[mt], bh[ns], bh[ns + 2]);
                    }
                }
            }
        }
        __syncthreads();
    }

    float* s_out = (float*)dsm;    // reuse pipeline smem: [BM][BN] relu'd tile
    auto emit = [&](int row, int col, float vx, float vy) {
        if (row >= M) return;
        if constexpr (FUSE_LSM) {
            s_out[(row - m0) * BN + col] = vx;
            s_out[(row - m0) * BN + col + 1] = vy;
        } else {
            float2 o; o.x = vx; o.y = vy;
            *(float2*)(C + (size_t)row * BN + col) = o;
            unsigned hi = (unsigned)bfh(vx) | ((unsigned)bfh(vy) << 16);
            unsigned lo = (unsigned)bfh(vx - bfhf(vx)) | ((unsigned)bfh(vy - bfhf(vy)) << 16);
            char* rp = (char*)(g_h2s + (size_t)row * 64);
            int byte = (col >> 3) * 32 + (col & 7) * 2;
            *(unsigned*)(rp + byte)      = hi;
            *(unsigned*)(rp + byte + 16) = lo;
        }
    };
#pragma unroll
    for (int mt = 0; mt < 2; mt++) {
#pragma unroll
        for (int j = 0; j < NTP * 2; j++) {
            int row = m0 + wm * 32 + mt * 16 + (lane >> 2);
            int col = wn * (BN / 4) + (j >> 1) * 16 + (j & 1) * 8 + (lane & 3) * 2;
            float bx = __ldg(&bias[col]), by = __ldg(&bias[col + 1]);
            emit(row, col, fmaxf(cacc[mt][j][0] + bx, 0.0f), fmaxf(cacc[mt][j][1] + by, 0.0f));
            emit(row + 8, col, fmaxf(cacc[mt][j][2] + bx, 0.0f), fmaxf(cacc[mt][j][3] + by, 0.0f));
        }
    }

    if constexpr (FUSE_LSM) {
        __syncthreads();
        // warp wid handles rows [8*wid, 8*wid+8); 128 cols -> 4 vals/lane
#pragma unroll
        for (int r8 = 0; r8 < 8; r8++) {
            int rl = wid * 8 + r8;
            int gr = m0 + rl;
            if (gr >= M) break;
            float v[4];
#pragma unroll
            for (int j = 0; j < 4; j++) v[j] = s_out[rl * 128 + lane + 32 * j];
            float mx = fmaxf(fmaxf(v[0], v[1]), fmaxf(v[2], v[3]));
#pragma unroll
            for (int o = 16; o > 0; o >>= 1) mx = fmaxf(mx, __shfl_xor_sync(~0u, mx, o));
            float s = 0.0f;
#pragma unroll
            for (int j = 0; j < 4; j++) s += expf(v[j] - mx);
#pragma unroll
            for (int o = 16; o > 0; o >>= 1) s += __shfl_xor_sync(~0u, s, o);
            float lse = mx + logf(s);
#pragma unroll
            for (int j = 0; j < 4; j++)
                Cout[(size_t)gr * 128 + lane + 32 * j] = v[j] - lse;
        }
    }
}

// ---------------- entry ----------------
extern "C" void kernel_launch(void* const* d_in, const int* in_sizes, int n_in,
                              void* d_out, int out_size) {
    const float* x      = (const float*)d_in[0];
    const int*   ei     = (const int*)  d_in[1];
    const float* pseudo = (const float*)d_in[2];
    const float* W1     = (const float*)d_in[3];
    const float* root1  = (const float*)d_in[4];
    const float* b1     = (const float*)d_in[5];
    const float* W2     = (const float*)d_in[6];
    const float* root2  = (const float*)d_in[7];
    const float* b2     = (const float*)d_in[8];
    const float* W3     = (const float*)d_in[9];
    const float* root3  = (const float*)d_in[10];
    const float* b3     = (const float*)d_in[11];
    float* out = (float*)d_out;
    int N = in_sizes[0];
    int E = in_sizes[1] / 2;

    const int SMEM2 = 4 * (64 * 128 + 64 * 128);    // 65536
    const int SMEM3 = 4 * (64 * 128 + 128 * 128);   // 98304
    cudaFuncSetAttribute(gemm_cp_kernel<1536, 32, 64>,
                         cudaFuncAttributeMaxDynamicSharedMemorySize, SMEM2);
    cudaFuncSetAttribute(gemm_cp_kernel<3072, 64, 128>,
                         cudaFuncAttributeMaxDynamicSharedMemorySize, SMEM3);

    int eb = (E + 255) / 256;
    int nb4 = (N + 3) / 4;
    precompute_kernel<<<eb, 256>>>(pseudo, ei, E);       // basis + hist (fused)
    prefix_kernel<<<1, 1024>>>();                        // scan + re-zero g_cnt
    order_kernel<<<eb, 256>>>(ei, E);
    layer1_kernel<<<nb4, 128>>>(x, W1, root1, b1, N);
    bsplit_kernel<1536, 32, 64><<<(64 * 196 + 255) / 256, 256>>>(W2, root2);
    bsplit_kernel<3072, 64, 128><<<(128 * 392 + 255) / 256, 256>>>(W3, root3);
    gather_scatter_kernel<32><<<nb4, 128>>>(N);
    gemm_cp_kernel<1536, 32, 64><<<(N + 63) / 64, 256, SMEM2>>>(b2, nullptr, N);
    gather_scatter_kernel<64><<<nb4, 128>>>(N);
    gemm_cp_kernel<3072, 64, 128><<<(N + 63) / 64, 256, SMEM3>>>(b3, out, N);
}